// round 14
// baseline (speedup 1.0000x reference)
#include <cuda_runtime.h>
#include <cuda_bf16.h>
#include <cstdint>
#include <cstddef>

// Problem shapes (fixed by the dataset)
#define Bn   8
#define Hn   4
#define Nn   2048
#define Dn   128
#define NCOL (Hn * Dn)   // 512 combined (h,o) columns in the aggregation GEMM

// ---------------------------------------------------------------------------
// Scratch (device globals — no allocations allowed)
// ---------------------------------------------------------------------------
__device__ float g_dinv[Bn * Nn];                            // d^-1/2 per (b,n)
__device__ float g_part[Bn][8][Nn];                          // partial column sums
__device__ __nv_bfloat16 g_adj16[(size_t)Bn * Nn * Nn];      // bf16 copy of adj
__device__ __nv_bfloat16 g_ssT16[(size_t)Bn * NCOL * Nn];    // scaled support, bf16, [b][col][n]

// ---------------------------------------------------------------------------
// Helpers
// ---------------------------------------------------------------------------
__device__ __forceinline__ float tf32r(float x) {
    unsigned u;
    asm("cvt.rna.tf32.f32 %0, %1;" : "=r"(u) : "f"(x));
    return __uint_as_float(u);
}

__device__ __forceinline__ void mma_tf32(float c[4], const unsigned a[4], const unsigned b[2]) {
    asm volatile(
        "mma.sync.aligned.m16n8k8.row.col.f32.tf32.tf32.f32 "
        "{%0,%1,%2,%3}, {%4,%5,%6,%7}, {%8,%9}, {%0,%1,%2,%3};\n"
        : "+f"(c[0]), "+f"(c[1]), "+f"(c[2]), "+f"(c[3])
        : "r"(a[0]), "r"(a[1]), "r"(a[2]), "r"(a[3]),
          "r"(b[0]), "r"(b[1]));
}

__device__ __forceinline__ void mma_bf16(float c[4], const unsigned a[4], const unsigned b[2]) {
    asm volatile(
        "mma.sync.aligned.m16n8k16.row.col.f32.bf16.bf16.f32 "
        "{%0,%1,%2,%3}, {%4,%5,%6,%7}, {%8,%9}, {%0,%1,%2,%3};\n"
        : "+f"(c[0]), "+f"(c[1]), "+f"(c[2]), "+f"(c[3])
        : "r"(a[0]), "r"(a[1]), "r"(a[2]), "r"(a[3]),
          "r"(b[0]), "r"(b[1]));
}

#define LDSM_X4(r0, r1, r2, r3, addr) \
    asm volatile("ldmatrix.sync.aligned.m8n8.x4.shared.b16 {%0,%1,%2,%3}, [%4];" \
                 : "=r"(r0), "=r"(r1), "=r"(r2), "=r"(r3) : "r"(addr))

__device__ __forceinline__ uint32_t smem_u32(const void* p) {
    uint32_t a;
    asm("{ .reg .u64 t; cvta.to.shared.u64 t, %1; cvt.u32.u64 %0, t; }" : "=r"(a) : "l"(p));
    return a;
}

#define CP_ASYNC16(dst, src) \
    asm volatile("cp.async.cg.shared.global [%0], [%1], 16;" :: "r"(dst), "l"(src) : "memory")
#define CP_COMMIT()  asm volatile("cp.async.commit_group;" ::: "memory")
#define CP_WAIT0()   asm volatile("cp.async.wait_group 0;" ::: "memory")
#define CP_WAIT1()   asm volatile("cp.async.wait_group 1;" ::: "memory")
#define CP_WAIT2()   asm volatile("cp.async.wait_group 2;" ::: "memory")

// fp32 tile layout for K2 (CTA 128x128, BK=32, 3 stages)
struct GStage {
    float As[128][36];
    float Bs[32][136];
};
#define G_SMEM (3 * (int)sizeof(GStage))

// bf16 tile layout for K3 (CTA 128(M) x 128(N), BK=32, 4 stages)
// Row pad 32->40 ushorts (80B): the 8 rows of each ldmatrix 8x8 land at byte
// offsets {0,80,32,112,64,16,96,48} mod 128 — all eight 16B chunks distinct
// => conflict-free LDSM.
struct K3Stage {
    unsigned short A[128][40];   // adj tile   [m][k]
    unsigned short B[128][40];   // support^T  [n][k]
};
#define K3_SMEM (4 * (int)sizeof(K3Stage))

// ---------------------------------------------------------------------------
// K1a: partial column sums of adj + fused fp32 copy + fused bf16 conversion.
// grid = Bn * 8(nchunk) * 8(msplit) = 512 blocks, 256 threads.
// ---------------------------------------------------------------------------
__global__ void __launch_bounds__(256) degree_partial_kernel(
    const float* __restrict__ adj, float* __restrict__ adj_copy)
{
    const int bid = blockIdx.x;
    const int s  = bid & 7;          // m-split
    const int nc = (bid >> 3) & 7;   // n-chunk
    const int b  = bid >> 6;

    const int n = nc * 256 + threadIdx.x;
    const float* p = adj + (size_t)b * Nn * Nn + n;
    float* q = adj_copy ? (adj_copy + (size_t)b * Nn * Nn + n) : nullptr;
    __nv_bfloat16* q16 = g_adj16 + (size_t)b * Nn * Nn + n;

    const int m0 = s * 256;
    float s0 = 0.f, s1 = 0.f, s2 = 0.f, s3 = 0.f;
    #pragma unroll 1
    for (int m = m0; m < m0 + 256; m += 8) {
        float v0 = p[(size_t)(m + 0) * Nn];
        float v1 = p[(size_t)(m + 1) * Nn];
        float v2 = p[(size_t)(m + 2) * Nn];
        float v3 = p[(size_t)(m + 3) * Nn];
        float v4 = p[(size_t)(m + 4) * Nn];
        float v5 = p[(size_t)(m + 5) * Nn];
        float v6 = p[(size_t)(m + 6) * Nn];
        float v7 = p[(size_t)(m + 7) * Nn];
        if (q) {
            q[(size_t)(m + 0) * Nn] = v0;
            q[(size_t)(m + 1) * Nn] = v1;
            q[(size_t)(m + 2) * Nn] = v2;
            q[(size_t)(m + 3) * Nn] = v3;
            q[(size_t)(m + 4) * Nn] = v4;
            q[(size_t)(m + 5) * Nn] = v5;
            q[(size_t)(m + 6) * Nn] = v6;
            q[(size_t)(m + 7) * Nn] = v7;
        }
        q16[(size_t)(m + 0) * Nn] = __float2bfloat16_rn(v0);
        q16[(size_t)(m + 1) * Nn] = __float2bfloat16_rn(v1);
        q16[(size_t)(m + 2) * Nn] = __float2bfloat16_rn(v2);
        q16[(size_t)(m + 3) * Nn] = __float2bfloat16_rn(v3);
        q16[(size_t)(m + 4) * Nn] = __float2bfloat16_rn(v4);
        q16[(size_t)(m + 5) * Nn] = __float2bfloat16_rn(v5);
        q16[(size_t)(m + 6) * Nn] = __float2bfloat16_rn(v6);
        q16[(size_t)(m + 7) * Nn] = __float2bfloat16_rn(v7);
        s0 += v0 + v4;
        s1 += v1 + v5;
        s2 += v2 + v6;
        s3 += v3 + v7;
    }
    g_part[b][s][n] = (s0 + s1) + (s2 + s3);
}

// K1b: reduce the 8 partials, d^{-1/2}
__global__ void degree_finish_kernel()
{
    const int idx = blockIdx.x * blockDim.x + threadIdx.x;   // 0 .. Bn*Nn-1
    const int b = idx >> 11;
    const int n = idx & (Nn - 1);
    float s = 0.f;
    #pragma unroll
    for (int k = 0; k < 8; k++) s += g_part[b][k][n];
    g_dinv[idx] = rsqrtf(s);
}

// ---------------------------------------------------------------------------
// K2: scaled support via tf32 mma (RNA fragments), epilogue transposes in smem
// and stores bf16 K-major:  g_ssT16[b][h*128+o][n] = bf16(d[b,n] * (x@W)[n][o])
// CTA 128(M=n) x 128(N=o), BK=32, NK=4. grid = Bn*Hn*16 = 512 blocks.
// ---------------------------------------------------------------------------
__global__ void __launch_bounds__(256, 2) support_tc_kernel(
    const float* __restrict__ x, const float* __restrict__ W)
{
    extern __shared__ GStage stages[];   // [3]

    const int bid = blockIdx.x;
    const int chunk = bid & 15;            // m-tile (n rows)
    const int h = (bid >> 4) & 3;
    const int b = bid >> 6;
    const int m0 = chunk * 128;

    const float* Ax = x + ((size_t)(b * Hn + h) * Nn) * Dn;
    const float* Bw = W + (size_t)h * Dn * Dn;

    const int t = threadIdx.x;
    const int lane = t & 31;
    const int warp = t >> 5;
    const int warpM = warp >> 2;           // 0..1
    const int warpN = warp & 3;            // 0..3
    const int gid = lane >> 2;             // 0..7
    const int tid4 = lane & 3;             // 0..3

    // cp.async staging (16B chunks)
    const int aRow = t >> 3;             // 0..31 (+32*i)
    const int aChk = t & 7;
    const int bRow = t >> 5;             // 0..7 (+8*i)
    const int bChk = t & 31;

    const char* aSrcBase = (const char*)(Ax + (size_t)(m0 + aRow) * Dn) + aChk * 16;
    const char* bSrcBase = (const char*)(Bw + (size_t)bRow * Dn) + bChk * 16;

    uint32_t aDst[3], bDst[3];
    #pragma unroll
    for (int s = 0; s < 3; s++) {
        aDst[s] = smem_u32(&stages[s].As[aRow][0]) + aChk * 16;
        bDst[s] = smem_u32(&stages[s].Bs[bRow][0]) + bChk * 16;
    }

    auto issue_stage = [&](int s, int kt) {
        const size_t kOffA = (size_t)kt * 32 * 4;
        const size_t kOffB = (size_t)kt * 32 * Dn * 4;
        #pragma unroll
        for (int i = 0; i < 4; i++)
            CP_ASYNC16(aDst[s] + i * 32 * (36 * 4),
                       aSrcBase + kOffA + (size_t)i * 32 * Dn * 4);
        #pragma unroll
        for (int i = 0; i < 4; i++)
            CP_ASYNC16(bDst[s] + i * 8 * (136 * 4),
                       bSrcBase + kOffB + (size_t)i * 8 * Dn * 4);
        CP_COMMIT();
    };

    float acc[4][4][4];
    #pragma unroll
    for (int mt = 0; mt < 4; mt++)
        #pragma unroll
        for (int nt = 0; nt < 4; nt++)
            #pragma unroll
            for (int i = 0; i < 4; i++) acc[mt][nt][i] = 0.f;

    issue_stage(0, 0);
    issue_stage(1, 1);

    const int NK = Dn / 32;   // 4
    #pragma unroll 1
    for (int kt = 0; kt < NK; ++kt) {
        if (kt < NK - 1) CP_WAIT1(); else CP_WAIT0();
        __syncthreads();
        if (kt + 2 < NK) issue_stage((kt + 2) % 3, kt + 2);

        const GStage& st = stages[kt % 3];

        #pragma unroll
        for (int ks = 0; ks < 4; ++ks) {
            const int koff = ks * 8;
            unsigned af[4][4];
            #pragma unroll
            for (int mt = 0; mt < 4; ++mt) {
                const int m = warpM * 64 + mt * 16;
                af[mt][0] = __float_as_uint(tf32r(st.As[m + gid    ][koff + tid4    ]));
                af[mt][1] = __float_as_uint(tf32r(st.As[m + gid + 8][koff + tid4    ]));
                af[mt][2] = __float_as_uint(tf32r(st.As[m + gid    ][koff + tid4 + 4]));
                af[mt][3] = __float_as_uint(tf32r(st.As[m + gid + 8][koff + tid4 + 4]));
            }
            unsigned bf[4][2];
            #pragma unroll
            for (int nt = 0; nt < 4; ++nt) {
                const int n = warpN * 32 + nt * 8 + gid;
                bf[nt][0] = __float_as_uint(tf32r(st.Bs[koff + tid4    ][n]));
                bf[nt][1] = __float_as_uint(tf32r(st.Bs[koff + tid4 + 4][n]));
            }
            #pragma unroll
            for (int mt = 0; mt < 4; ++mt)
                #pragma unroll
                for (int nt = 0; nt < 4; ++nt)
                    mma_tf32(acc[mt][nt], af[mt], bf[nt]);
        }
    }

    // Epilogue: d-scale, bf16, transpose via smem, store K-major rows.
    __syncthreads();   // all warps done reading stages; reuse smem
    unsigned short (*tsp)[136] = (unsigned short(*)[136])stages;   // [128 o][136 pad n]

    #pragma unroll
    for (int mt = 0; mt < 4; ++mt) {
        const int ml = warpM * 64 + mt * 16 + gid;          // local n-row
        const float dv0 = g_dinv[b * Nn + m0 + ml];
        const float dv1 = g_dinv[b * Nn + m0 + ml + 8];
        #pragma unroll
        for (int nt = 0; nt < 4; ++nt) {
            const int o = warpN * 32 + nt * 8 + 2 * tid4;
            tsp[o    ][ml    ] = __bfloat16_as_ushort(__float2bfloat16_rn(acc[mt][nt][0] * dv0));
            tsp[o + 1][ml    ] = __bfloat16_as_ushort(__float2bfloat16_rn(acc[mt][nt][1] * dv0));
            tsp[o    ][ml + 8] = __bfloat16_as_ushort(__float2bfloat16_rn(acc[mt][nt][2] * dv1));
            tsp[o + 1][ml + 8] = __bfloat16_as_ushort(__float2bfloat16_rn(acc[mt][nt][3] * dv1));
        }
    }
    __syncthreads();

    // write rows: 128 o-rows x 128 bf16; thread t -> row t>>1, half t&1
    {
        const int o = t >> 1;
        const int half = t & 1;
        const uint4* src = (const uint4*)&tsp[o][half * 64];
        uint4* dst = (uint4*)(g_ssT16 + ((size_t)b * NCOL + h * Dn + o) * Nn + m0 + half * 64);
        #pragma unroll
        for (int j = 0; j < 8; j++) dst[j] = src[j];
    }
}

// ---------------------------------------------------------------------------
// K3 v7: aggregation GEMM, bf16 mma m16n8k16 with LDMATRIX fragment loads.
// CTA 128(M) x 128(N), 8 warps (2x4), warp tile 64x32, BK=32, 4-stage ring.
// Per warp-ktile: 12 ldmatrix.x4 replace 48 scalar LDS.
// grid = Bn * 16(mtile) * 4(h) = 512, h fastest (L2 reuse of adj rows).
// ---------------------------------------------------------------------------
__global__ void __launch_bounds__(256, 2) aggregate_kernel(
    const float* __restrict__ bias,
    float* __restrict__ out)
{
    extern __shared__ K3Stage stg[];   // [4]

    const int bid = blockIdx.x;
    const int h = bid & 3;
    const int mtile = (bid >> 2) & 15;
    const int b = bid >> 6;
    const int m0 = mtile * 128;
    const int col0 = h * 128;

    const int t = threadIdx.x;
    const int lane = t & 31;
    const int warp = t >> 5;
    const int warpM = warp >> 2;           // 0..1  (64 M-rows each)
    const int warpN = warp & 3;            // 0..3  (32 N-cols each)
    const int gid = lane >> 2;             // 0..7
    const int tid4 = lane & 3;             // 0..3

    // staging: thread t -> row t>>1 (0..127), 32B half (t&1); 2 chunks each side
    const int sRow = t >> 1;
    const int sHalf = (t & 1) * 32;

    const char* aSrc = (const char*)(g_adj16 + ((size_t)b * Nn + m0 + sRow) * Nn) + sHalf;
    const char* bSrc = (const char*)(g_ssT16 + ((size_t)b * NCOL + col0 + sRow) * Nn) + sHalf;

    uint32_t aDst[4], bDst[4];
    #pragma unroll
    for (int s = 0; s < 4; s++) {
        aDst[s] = smem_u32(&stg[s].A[sRow][0]) + sHalf;
        bDst[s] = smem_u32(&stg[s].B[sRow][0]) + sHalf;
    }

    auto issue_stage = [&](int s, int kt) {
        const size_t off = (size_t)kt * 64;   // 32 bf16 = 64 B along k
        CP_ASYNC16(aDst[s],      aSrc + off);
        CP_ASYNC16(aDst[s] + 16, aSrc + off + 16);
        CP_ASYNC16(bDst[s],      bSrc + off);
        CP_ASYNC16(bDst[s] + 16, bSrc + off + 16);
        CP_COMMIT();
    };

    // ldmatrix per-thread fragment addresses:
    // row = base + (lane & 15), col-byte = ((lane >> 4) << 3) * 2
    const int lRow = lane & 15;
    const int lColB = ((lane >> 4) << 3) * 2;   // 0 or 16 bytes
    uint32_t aFrag[4], bFrag[4];
    #pragma unroll
    for (int s = 0; s < 4; s++) {
        aFrag[s] = smem_u32(&stg[s].A[warpM * 64 + lRow][0]) + lColB;
        bFrag[s] = smem_u32(&stg[s].B[warpN * 32 + lRow][0]) + lColB;
    }
    const uint32_t ROWB = 40 * 2;               // row stride bytes

    float acc[4][4][4];
    #pragma unroll
    for (int mt = 0; mt < 4; mt++)
        #pragma unroll
        for (int nt = 0; nt < 4; nt++)
            #pragma unroll
            for (int i = 0; i < 4; i++) acc[mt][nt][i] = 0.f;

    issue_stage(0, 0);
    issue_stage(1, 1);
    issue_stage(2, 2);

    const int NK = Nn / 32;   // 64
    #pragma unroll 1
    for (int kt = 0; kt < NK; ++kt) {
        CP_WAIT2();            // committed = kt+3; <=2 pending => group kt done
        __syncthreads();
        // Slot (kt+3)%4 was consumed at iter kt-1; all warps are past that
        // compute (they reached this barrier), so reissue is race-free.
        if (kt + 3 < NK) issue_stage((kt + 3) & 3, kt + 3);
        else             CP_COMMIT();   // keep group count uniform

        const int sl = kt & 3;
        const uint32_t aF = aFrag[sl];
        const uint32_t bF = bFrag[sl];

        #pragma unroll
        for (int ks = 0; ks < 2; ++ks) {
            const uint32_t kOff = (uint32_t)ks * 32;     // 16 bf16 = 32 B
            // A fragments: 4 x (16x16) tiles => regs in m16n8k16 order
            unsigned af[4][4];
            #pragma unroll
            for (int mt = 0; mt < 4; ++mt)
                LDSM_X4(af[mt][0], af[mt][1], af[mt][2], af[mt][3],
                        aF + (uint32_t)mt * 16 * ROWB + kOff);
            // B fragments: 2 x (16n x 16k) tiles => nt pairs, (b0,b1) halves
            unsigned bf[4][2];
            #pragma unroll
            for (int p = 0; p < 2; ++p)
                LDSM_X4(bf[2 * p][0], bf[2 * p + 1][0], bf[2 * p][1], bf[2 * p + 1][1],
                        bF + (uint32_t)p * 16 * ROWB + kOff);
            #pragma unroll
            for (int mt = 0; mt < 4; ++mt)
                #pragma unroll
                for (int nt = 0; nt < 4; ++nt)
                    mma_bf16(acc[mt][nt], af[mt], bf[nt]);
        }
    }

    // Epilogue: scale by d[b,m], add bias[h,o], tanh, store to out[b,h,m,o]
    const float* biasH = bias + h * Dn;
    #pragma unroll
    for (int mt = 0; mt < 4; ++mt) {
        const int mA = m0 + warpM * 64 + mt * 16 + gid;
        const float dv0 = g_dinv[b * Nn + mA];
        const float dv1 = g_dinv[b * Nn + mA + 8];
        #pragma unroll
        for (int nt = 0; nt < 4; ++nt) {
            const int o = warpN * 32 + nt * 8 + 2 * tid4;
            const float bz0 = biasH[o];
            const float bz1 = biasH[o + 1];
            float* dst0 = out + ((size_t)(b * Hn + h) * Nn + mA) * Dn + o;
            float* dst1 = dst0 + (size_t)8 * Dn;
            float2 v0, v1;
            v0.x = tanhf(acc[mt][nt][0] * dv0 + bz0);
            v0.y = tanhf(acc[mt][nt][1] * dv0 + bz1);
            v1.x = tanhf(acc[mt][nt][2] * dv1 + bz0);
            v1.y = tanhf(acc[mt][nt][3] * dv1 + bz1);
            *(float2*)dst0 = v0;
            *(float2*)dst1 = v1;
        }
    }
}

// ---------------------------------------------------------------------------
// Launch
// ---------------------------------------------------------------------------
extern "C" void kernel_launch(void* const* d_in, const int* in_sizes, int n_in,
                              void* d_out, int out_size)
{
    const float* x      = (const float*)d_in[0];   // [B,H,N,Din]
    const float* adj    = (const float*)d_in[1];   // [B,N,N]
    const float* pooled = (const float*)d_in[2];   // [B,Dout]
    const float* W      = (const float*)d_in[3];   // [H,Din,Dout]
    const float* bias   = (const float*)d_in[4];   // [H,Dout]
    float* out = (float*)d_out;

    const size_t outElems  = (size_t)Bn * Hn * Nn * Dn;   // 8388608
    const size_t adjElems  = (size_t)in_sizes[1];          // 33554432
    const size_t poolElems = (size_t)in_sizes[2];          // 1024

    const bool fullOut = (size_t)out_size >= outElems + adjElems + poolElems;
    float* adjCopy = fullOut ? (out + outElems) : nullptr;

    // pooled pass-through
    if (fullOut) {
        cudaMemcpyAsync(out + outElems + adjElems, pooled,
                        poolElems * sizeof(float), cudaMemcpyDeviceToDevice, 0);
    }

    cudaFuncSetAttribute(aggregate_kernel,
                         cudaFuncAttributeMaxDynamicSharedMemorySize, K3_SMEM);
    cudaFuncSetAttribute(support_tc_kernel,
                         cudaFuncAttributeMaxDynamicSharedMemorySize, G_SMEM);

    // K1: degrees (+ fused fp32 copy + bf16 conversion)
    degree_partial_kernel<<<Bn * 8 * 8, 256>>>(adj, adjCopy);
    degree_finish_kernel<<<(Bn * Nn) / 256, 256>>>();

    // K2: scaled support (tf32 tensor cores, bf16 transposed output)
    support_tc_kernel<<<Bn * Hn * (Nn / 128), 256, G_SMEM>>>(x, W);

    // K3: aggregation (bf16 tensor cores, ldmatrix) + fused epilogue
    aggregate_kernel<<<Bn * (Nn / 128) * Hn, 256, K3_SMEM>>>(bias, out);
}

// round 15
// speedup vs baseline: 1.2202x; 1.2202x over previous
#include <cuda_runtime.h>
#include <cuda_bf16.h>
#include <cstdint>
#include <cstddef>

// Problem shapes (fixed by the dataset)
#define Bn   8
#define Hn   4
#define Nn   2048
#define Dn   128
#define NCOL (Hn * Dn)   // 512 combined (h,o) columns in the aggregation GEMM

// ---------------------------------------------------------------------------
// Scratch (device globals — no allocations allowed)
// ---------------------------------------------------------------------------
__device__ float g_dinv[Bn * Nn];                            // d^-1/2 per (b,n)
__device__ float g_part[Bn][8][Nn];                          // partial column sums
__device__ __nv_bfloat16 g_adj16[(size_t)Bn * Nn * Nn];      // bf16 copy of adj
__device__ __nv_bfloat16 g_ssT16[(size_t)Bn * NCOL * Nn];    // scaled support, bf16, [b][col][n]

// ---------------------------------------------------------------------------
// Helpers
// ---------------------------------------------------------------------------
__device__ __forceinline__ float tf32r(float x) {
    unsigned u;
    asm("cvt.rna.tf32.f32 %0, %1;" : "=r"(u) : "f"(x));
    return __uint_as_float(u);
}

__device__ __forceinline__ void mma_tf32(float c[4], const unsigned a[4], const unsigned b[2]) {
    asm volatile(
        "mma.sync.aligned.m16n8k8.row.col.f32.tf32.tf32.f32 "
        "{%0,%1,%2,%3}, {%4,%5,%6,%7}, {%8,%9}, {%0,%1,%2,%3};\n"
        : "+f"(c[0]), "+f"(c[1]), "+f"(c[2]), "+f"(c[3])
        : "r"(a[0]), "r"(a[1]), "r"(a[2]), "r"(a[3]),
          "r"(b[0]), "r"(b[1]));
}

__device__ __forceinline__ void mma_bf16(float c[4], const unsigned a[4], const unsigned b[2]) {
    asm volatile(
        "mma.sync.aligned.m16n8k16.row.col.f32.bf16.bf16.f32 "
        "{%0,%1,%2,%3}, {%4,%5,%6,%7}, {%8,%9}, {%0,%1,%2,%3};\n"
        : "+f"(c[0]), "+f"(c[1]), "+f"(c[2]), "+f"(c[3])
        : "r"(a[0]), "r"(a[1]), "r"(a[2]), "r"(a[3]),
          "r"(b[0]), "r"(b[1]));
}

#define LDSM_X4(r0, r1, r2, r3, addr) \
    asm volatile("ldmatrix.sync.aligned.m8n8.x4.shared.b16 {%0,%1,%2,%3}, [%4];" \
                 : "=r"(r0), "=r"(r1), "=r"(r2), "=r"(r3) : "r"(addr))

__device__ __forceinline__ uint32_t smem_u32(const void* p) {
    uint32_t a;
    asm("{ .reg .u64 t; cvta.to.shared.u64 t, %1; cvt.u32.u64 %0, t; }" : "=r"(a) : "l"(p));
    return a;
}

#define CP_ASYNC16(dst, src) \
    asm volatile("cp.async.cg.shared.global [%0], [%1], 16;" :: "r"(dst), "l"(src) : "memory")
#define CP_COMMIT()  asm volatile("cp.async.commit_group;" ::: "memory")
#define CP_WAIT0()   asm volatile("cp.async.wait_group 0;" ::: "memory")
#define CP_WAIT1()   asm volatile("cp.async.wait_group 1;" ::: "memory")
#define CP_WAIT2()   asm volatile("cp.async.wait_group 2;" ::: "memory")

// fp32 tile layout for K2 (CTA 128x128, BK=32, 3 stages)
struct GStage {
    float As[128][36];
    float Bs[32][136];
};
#define G_SMEM (3 * (int)sizeof(GStage))

// bf16 tile layout for K3 (CTA 64(M) x 128(N), BK=32, 4 stages)
// Row pad 32->40 ushorts (80B): the 8 rows of each ldmatrix 8x8 land at byte
// offsets {0,80,32,112,64,16,96,48} mod 128 — all eight 16B chunks distinct
// => conflict-free LDSM.
struct K3Stage {
    unsigned short A[64][40];    // adj tile   [m][k]
    unsigned short B[128][40];   // support^T  [n][k]
};
#define K3_STAGE_B ((int)sizeof(K3Stage))   // 15360
#define K3_SMEM (4 * K3_STAGE_B)

// ---------------------------------------------------------------------------
// K1a: partial column sums of adj + fused fp32 copy + fused bf16 conversion.
// grid = Bn * 8(nchunk) * 8(msplit) = 512 blocks, 256 threads.
// ---------------------------------------------------------------------------
__global__ void __launch_bounds__(256) degree_partial_kernel(
    const float* __restrict__ adj, float* __restrict__ adj_copy)
{
    const int bid = blockIdx.x;
    const int s  = bid & 7;          // m-split
    const int nc = (bid >> 3) & 7;   // n-chunk
    const int b  = bid >> 6;

    const int n = nc * 256 + threadIdx.x;
    const float* p = adj + (size_t)b * Nn * Nn + n;
    float* q = adj_copy ? (adj_copy + (size_t)b * Nn * Nn + n) : nullptr;
    __nv_bfloat16* q16 = g_adj16 + (size_t)b * Nn * Nn + n;

    const int m0 = s * 256;
    float s0 = 0.f, s1 = 0.f, s2 = 0.f, s3 = 0.f;
    #pragma unroll 1
    for (int m = m0; m < m0 + 256; m += 8) {
        float v0 = p[(size_t)(m + 0) * Nn];
        float v1 = p[(size_t)(m + 1) * Nn];
        float v2 = p[(size_t)(m + 2) * Nn];
        float v3 = p[(size_t)(m + 3) * Nn];
        float v4 = p[(size_t)(m + 4) * Nn];
        float v5 = p[(size_t)(m + 5) * Nn];
        float v6 = p[(size_t)(m + 6) * Nn];
        float v7 = p[(size_t)(m + 7) * Nn];
        if (q) {
            q[(size_t)(m + 0) * Nn] = v0;
            q[(size_t)(m + 1) * Nn] = v1;
            q[(size_t)(m + 2) * Nn] = v2;
            q[(size_t)(m + 3) * Nn] = v3;
            q[(size_t)(m + 4) * Nn] = v4;
            q[(size_t)(m + 5) * Nn] = v5;
            q[(size_t)(m + 6) * Nn] = v6;
            q[(size_t)(m + 7) * Nn] = v7;
        }
        q16[(size_t)(m + 0) * Nn] = __float2bfloat16_rn(v0);
        q16[(size_t)(m + 1) * Nn] = __float2bfloat16_rn(v1);
        q16[(size_t)(m + 2) * Nn] = __float2bfloat16_rn(v2);
        q16[(size_t)(m + 3) * Nn] = __float2bfloat16_rn(v3);
        q16[(size_t)(m + 4) * Nn] = __float2bfloat16_rn(v4);
        q16[(size_t)(m + 5) * Nn] = __float2bfloat16_rn(v5);
        q16[(size_t)(m + 6) * Nn] = __float2bfloat16_rn(v6);
        q16[(size_t)(m + 7) * Nn] = __float2bfloat16_rn(v7);
        s0 += v0 + v4;
        s1 += v1 + v5;
        s2 += v2 + v6;
        s3 += v3 + v7;
    }
    g_part[b][s][n] = (s0 + s1) + (s2 + s3);
}

// K1b: reduce the 8 partials, d^{-1/2}
__global__ void degree_finish_kernel()
{
    const int idx = blockIdx.x * blockDim.x + threadIdx.x;   // 0 .. Bn*Nn-1
    const int b = idx >> 11;
    const int n = idx & (Nn - 1);
    float s = 0.f;
    #pragma unroll
    for (int k = 0; k < 8; k++) s += g_part[b][k][n];
    g_dinv[idx] = rsqrtf(s);
}

// ---------------------------------------------------------------------------
// K2: scaled support via tf32 mma (RNA fragments), epilogue transposes in smem
// and stores bf16 K-major:  g_ssT16[b][h*128+o][n] = bf16(d[b,n] * (x@W)[n][o])
// CTA 128(M=n) x 128(N=o), BK=32, NK=4. grid = Bn*Hn*16 = 512 blocks.
// ---------------------------------------------------------------------------
__global__ void __launch_bounds__(256, 2) support_tc_kernel(
    const float* __restrict__ x, const float* __restrict__ W)
{
    extern __shared__ GStage stages[];   // [3]

    const int bid = blockIdx.x;
    const int chunk = bid & 15;            // m-tile (n rows)
    const int h = (bid >> 4) & 3;
    const int b = bid >> 6;
    const int m0 = chunk * 128;

    const float* Ax = x + ((size_t)(b * Hn + h) * Nn) * Dn;
    const float* Bw = W + (size_t)h * Dn * Dn;

    const int t = threadIdx.x;
    const int lane = t & 31;
    const int warp = t >> 5;
    const int warpM = warp >> 2;           // 0..1
    const int warpN = warp & 3;            // 0..3
    const int gid = lane >> 2;             // 0..7
    const int tid4 = lane & 3;             // 0..3

    // cp.async staging (16B chunks)
    const int aRow = t >> 3;             // 0..31 (+32*i)
    const int aChk = t & 7;
    const int bRow = t >> 5;             // 0..7 (+8*i)
    const int bChk = t & 31;

    const char* aSrcBase = (const char*)(Ax + (size_t)(m0 + aRow) * Dn) + aChk * 16;
    const char* bSrcBase = (const char*)(Bw + (size_t)bRow * Dn) + bChk * 16;

    uint32_t aDst[3], bDst[3];
    #pragma unroll
    for (int s = 0; s < 3; s++) {
        aDst[s] = smem_u32(&stages[s].As[aRow][0]) + aChk * 16;
        bDst[s] = smem_u32(&stages[s].Bs[bRow][0]) + bChk * 16;
    }

    auto issue_stage = [&](int s, int kt) {
        const size_t kOffA = (size_t)kt * 32 * 4;
        const size_t kOffB = (size_t)kt * 32 * Dn * 4;
        #pragma unroll
        for (int i = 0; i < 4; i++)
            CP_ASYNC16(aDst[s] + i * 32 * (36 * 4),
                       aSrcBase + kOffA + (size_t)i * 32 * Dn * 4);
        #pragma unroll
        for (int i = 0; i < 4; i++)
            CP_ASYNC16(bDst[s] + i * 8 * (136 * 4),
                       bSrcBase + kOffB + (size_t)i * 8 * Dn * 4);
        CP_COMMIT();
    };

    float acc[4][4][4];
    #pragma unroll
    for (int mt = 0; mt < 4; mt++)
        #pragma unroll
        for (int nt = 0; nt < 4; nt++)
            #pragma unroll
            for (int i = 0; i < 4; i++) acc[mt][nt][i] = 0.f;

    issue_stage(0, 0);
    issue_stage(1, 1);

    const int NK = Dn / 32;   // 4
    #pragma unroll 1
    for (int kt = 0; kt < NK; ++kt) {
        if (kt < NK - 1) CP_WAIT1(); else CP_WAIT0();
        __syncthreads();
        if (kt + 2 < NK) issue_stage((kt + 2) % 3, kt + 2);

        const GStage& st = stages[kt % 3];

        #pragma unroll
        for (int ks = 0; ks < 4; ++ks) {
            const int koff = ks * 8;
            unsigned af[4][4];
            #pragma unroll
            for (int mt = 0; mt < 4; ++mt) {
                const int m = warpM * 64 + mt * 16;
                af[mt][0] = __float_as_uint(tf32r(st.As[m + gid    ][koff + tid4    ]));
                af[mt][1] = __float_as_uint(tf32r(st.As[m + gid + 8][koff + tid4    ]));
                af[mt][2] = __float_as_uint(tf32r(st.As[m + gid    ][koff + tid4 + 4]));
                af[mt][3] = __float_as_uint(tf32r(st.As[m + gid + 8][koff + tid4 + 4]));
            }
            unsigned bf[4][2];
            #pragma unroll
            for (int nt = 0; nt < 4; ++nt) {
                const int n = warpN * 32 + nt * 8 + gid;
                bf[nt][0] = __float_as_uint(tf32r(st.Bs[koff + tid4    ][n]));
                bf[nt][1] = __float_as_uint(tf32r(st.Bs[koff + tid4 + 4][n]));
            }
            #pragma unroll
            for (int mt = 0; mt < 4; ++mt)
                #pragma unroll
                for (int nt = 0; nt < 4; ++nt)
                    mma_tf32(acc[mt][nt], af[mt], bf[nt]);
        }
    }

    // Epilogue: d-scale, bf16, transpose via smem, store K-major rows.
    __syncthreads();   // all warps done reading stages; reuse smem
    unsigned short (*tsp)[136] = (unsigned short(*)[136])stages;   // [128 o][136 pad n]

    #pragma unroll
    for (int mt = 0; mt < 4; ++mt) {
        const int ml = warpM * 64 + mt * 16 + gid;          // local n-row
        const float dv0 = g_dinv[b * Nn + m0 + ml];
        const float dv1 = g_dinv[b * Nn + m0 + ml + 8];
        #pragma unroll
        for (int nt = 0; nt < 4; ++nt) {
            const int o = warpN * 32 + nt * 8 + 2 * tid4;
            tsp[o    ][ml    ] = __bfloat16_as_ushort(__float2bfloat16_rn(acc[mt][nt][0] * dv0));
            tsp[o + 1][ml    ] = __bfloat16_as_ushort(__float2bfloat16_rn(acc[mt][nt][1] * dv0));
            tsp[o    ][ml + 8] = __bfloat16_as_ushort(__float2bfloat16_rn(acc[mt][nt][2] * dv1));
            tsp[o + 1][ml + 8] = __bfloat16_as_ushort(__float2bfloat16_rn(acc[mt][nt][3] * dv1));
        }
    }
    __syncthreads();

    // write rows: 128 o-rows x 128 bf16; thread t -> row t>>1, half t&1
    {
        const int o = t >> 1;
        const int half = t & 1;
        const uint4* src = (const uint4*)&tsp[o][half * 64];
        uint4* dst = (uint4*)(g_ssT16 + ((size_t)b * NCOL + h * Dn + o) * Nn + m0 + half * 64);
        #pragma unroll
        for (int j = 0; j < 8; j++) dst[j] = src[j];
    }
}

// ---------------------------------------------------------------------------
// K3 v9: bf16 mma m16n8k16 + LDSM fragments, CTA 64(M)x128(N), warp 32x32,
// 4-stage cp.async ring, main loop UNROLLED BY 4 (all stage indices literal),
// 3 CTAs/SM (24 warps).
// grid = Bn * 32(mtile) * 4(h) = 1024, h fastest (L2 reuse of adj rows).
// ---------------------------------------------------------------------------
__global__ void __launch_bounds__(256, 3) aggregate_kernel(
    const float* __restrict__ bias,
    float* __restrict__ out)
{
    extern __shared__ unsigned char k3smem[];
    K3Stage* stg = (K3Stage*)k3smem;   // [4]

    const int bid = blockIdx.x;
    const int h = bid & 3;
    const int mtile = (bid >> 2) & 31;
    const int b = bid >> 7;
    const int m0 = mtile * 64;
    const int col0 = h * 128;

    const int t = threadIdx.x;
    const int lane = t & 31;
    const int warp = t >> 5;
    const int warpM = warp >> 2;           // 0..1  (32 M-rows each)
    const int warpN = warp & 3;            // 0..3  (32 N-cols each)
    const int gid = lane >> 2;             // 0..7
    const int tid4 = lane & 3;             // 0..3

    // staging: 768 16B-chunks/stage (A 256, B 512); 3 per thread.
    const int sRow = t >> 2;               // 0..63
    const int sChk = (t & 3) * 16;         // byte offset within 64B k-row

    const char* aSrc  = (const char*)(g_adj16 + ((size_t)b * Nn + m0 + sRow) * Nn) + sChk;
    const char* bSrc0 = (const char*)(g_ssT16 + ((size_t)b * NCOL + col0 + sRow) * Nn) + sChk;
    const char* bSrc1 = bSrc0 + (size_t)64 * Nn * 2;

    const uint32_t aDstB  = smem_u32(&stg[0].A[sRow][0]) + sChk;
    const uint32_t bDst0B = smem_u32(&stg[0].B[sRow][0]) + sChk;
    const uint32_t bDst1B = smem_u32(&stg[0].B[sRow + 64][0]) + sChk;

    auto issue_stage = [&](int s, int kt) {   // s is compile-time after unroll
        const uint32_t so = (uint32_t)s * K3_STAGE_B;
        const size_t off = (size_t)kt * 64;   // 32 bf16 = 64 B along k
        CP_ASYNC16(aDstB  + so, aSrc  + off);
        CP_ASYNC16(bDst0B + so, bSrc0 + off);
        CP_ASYNC16(bDst1B + so, bSrc1 + off);
        CP_COMMIT();
    };

    // ldmatrix fragment base addresses (stage 0); stage offset added as literal
    const int lRow = lane & 15;
    const int lColB = (lane >> 4) * 16;    // 0 or 16 bytes (k half)
    const uint32_t aFragB = smem_u32(&stg[0].A[warpM * 32 + lRow][0]) + lColB;
    const uint32_t bFragB = smem_u32(&stg[0].B[warpN * 32 + lRow][0]) + lColB;
    const uint32_t ROWB = 40 * 2;          // row stride bytes

    float acc[2][4][4];
    #pragma unroll
    for (int mt = 0; mt < 2; mt++)
        #pragma unroll
        for (int nt = 0; nt < 4; nt++)
            #pragma unroll
            for (int i = 0; i < 4; i++) acc[mt][nt][i] = 0.f;

    auto compute = [&](int slot) {         // slot is compile-time after unroll
        const uint32_t so = (uint32_t)slot * K3_STAGE_B;
        #pragma unroll
        for (int ks = 0; ks < 2; ++ks) {
            const uint32_t kOff = so + (uint32_t)ks * 32;   // 16 bf16 = 32 B
            unsigned af[2][4];
            LDSM_X4(af[0][0], af[0][1], af[0][2], af[0][3], aFragB + kOff);
            LDSM_X4(af[1][0], af[1][1], af[1][2], af[1][3], aFragB + kOff + 16 * ROWB);
            unsigned bf[4][2];
            LDSM_X4(bf[0][0], bf[1][0], bf[0][1], bf[1][1], bFragB + kOff);
            LDSM_X4(bf[2][0], bf[3][0], bf[2][1], bf[3][1], bFragB + kOff + 16 * ROWB);
            #pragma unroll
            for (int mt = 0; mt < 2; ++mt)
                #pragma unroll
                for (int nt = 0; nt < 4; ++nt)
                    mma_bf16(acc[mt][nt], af[mt], bf[nt]);
        }
    };

    issue_stage(0, 0);
    issue_stage(1, 1);
    issue_stage(2, 2);

    const int NK = Nn / 32;   // 64
    #pragma unroll 1
    for (int kt4 = 0; kt4 < NK / 4; ++kt4) {
        #pragma unroll
        for (int j = 0; j < 4; ++j) {
            const int kt = kt4 * 4 + j;    // slot = j (kt4*4 ≡ 0 mod 4)
            CP_WAIT2();
            __syncthreads();
            // Slot (j+3)&3 was consumed at iter kt-1; all warps are past that
            // compute (they reached this barrier), so reissue is race-free.
            if (kt + 3 < NK) issue_stage((j + 3) & 3, kt + 3);
            else             CP_COMMIT();   // keep group count uniform
            compute(j);
        }
    }

    // Epilogue: scale by d[b,m], add bias[h,o], tanh, store to out[b,h,m,o]
    const float* biasH = bias + h * Dn;
    #pragma unroll
    for (int mt = 0; mt < 2; ++mt) {
        const int mA = m0 + warpM * 32 + mt * 16 + gid;
        const float dv0 = g_dinv[b * Nn + mA];
        const float dv1 = g_dinv[b * Nn + mA + 8];
        #pragma unroll
        for (int nt = 0; nt < 4; ++nt) {
            const int o = warpN * 32 + nt * 8 + 2 * tid4;
            const float bz0 = biasH[o];
            const float bz1 = biasH[o + 1];
            float* dst0 = out + ((size_t)(b * Hn + h) * Nn + mA) * Dn + o;
            float* dst1 = dst0 + (size_t)8 * Dn;
            float2 v0, v1;
            v0.x = tanhf(acc[mt][nt][0] * dv0 + bz0);
            v0.y = tanhf(acc[mt][nt][1] * dv0 + bz1);
            v1.x = tanhf(acc[mt][nt][2] * dv1 + bz0);
            v1.y = tanhf(acc[mt][nt][3] * dv1 + bz1);
            *(float2*)dst0 = v0;
            *(float2*)dst1 = v1;
        }
    }
}

// ---------------------------------------------------------------------------
// Launch
// ---------------------------------------------------------------------------
extern "C" void kernel_launch(void* const* d_in, const int* in_sizes, int n_in,
                              void* d_out, int out_size)
{
    const float* x      = (const float*)d_in[0];   // [B,H,N,Din]
    const float* adj    = (const float*)d_in[1];   // [B,N,N]
    const float* pooled = (const float*)d_in[2];   // [B,Dout]
    const float* W      = (const float*)d_in[3];   // [H,Din,Dout]
    const float* bias   = (const float*)d_in[4];   // [H,Dout]
    float* out = (float*)d_out;

    const size_t outElems  = (size_t)Bn * Hn * Nn * Dn;   // 8388608
    const size_t adjElems  = (size_t)in_sizes[1];          // 33554432
    const size_t poolElems = (size_t)in_sizes[2];          // 1024

    const bool fullOut = (size_t)out_size >= outElems + adjElems + poolElems;
    float* adjCopy = fullOut ? (out + outElems) : nullptr;

    // pooled pass-through
    if (fullOut) {
        cudaMemcpyAsync(out + outElems + adjElems, pooled,
                        poolElems * sizeof(float), cudaMemcpyDeviceToDevice, 0);
    }

    cudaFuncSetAttribute(aggregate_kernel,
                         cudaFuncAttributeMaxDynamicSharedMemorySize, K3_SMEM);
    cudaFuncSetAttribute(support_tc_kernel,
                         cudaFuncAttributeMaxDynamicSharedMemorySize, G_SMEM);

    // K1: degrees (+ fused fp32 copy + bf16 conversion)
    degree_partial_kernel<<<Bn * 8 * 8, 256>>>(adj, adjCopy);
    degree_finish_kernel<<<(Bn * Nn) / 256, 256>>>();

    // K2: scaled support (tf32 tensor cores, bf16 transposed output)
    support_tc_kernel<<<Bn * Hn * (Nn / 128), 256, G_SMEM>>>(x, W);

    // K3: aggregation (bf16 tensor cores, ldmatrix, 3 CTA/SM) + fused epilogue
    aggregate_kernel<<<Bn * (Nn / 64) * Hn, 256, K3_SMEM>>>(bias, out);
}